// round 2
// baseline (speedup 1.0000x reference)
#include <cuda_runtime.h>
#include <cstdint>

#define BB 4
#define NNODE 2048
#define FF 64
#define FPD 32
#define HH 4
#define IT 32          // rows per block in attention kernel
#define JT 64          // j tile
#define CH (HH*FPD)    // 128 output channels
#define OUT_MAIN (BB*NNODE*CH)   // 1048576
#define NBLK (BB*(NNODE/IT))     // 256 attention blocks

// ---------------- device scratch (no allocs allowed) ----------------
__device__ float g_feats[(size_t)BB*HH*NNODE*FPD];  // [(b*H+h)*N + n]*FP + d
__device__ float g_s[BB*HH*NNODE];
__device__ float g_t[BB*HH*NNODE];
__device__ float g_tmax[BB*HH];
__device__ float g_lossu[NBLK];
__device__ float g_losse[NBLK];

// ==================== kernel 1: feats = x@W, s, t ====================
struct SmemF {
  float Ws[HH][FF][FPD];   // 32 KB
  float xs[64][FF+1];      // pad -> conflict-free xs[nl][f] reads
  float as_s[HH][FPD];
  float an_s[HH][FPD];
};

__global__ void __launch_bounds__(256) k_feats(const float* __restrict__ x,
    const float* __restrict__ W, const float* __restrict__ a_self,
    const float* __restrict__ a_neigh) {
  extern __shared__ char raw_f[];
  SmemF& S = *reinterpret_cast<SmemF*>(raw_f);
  const int tid = threadIdx.x;
  const int b = blockIdx.y;
  const int n0 = blockIdx.x * 64;

  {
    const float4* src = reinterpret_cast<const float4*>(W);
    float4* dst = reinterpret_cast<float4*>(&S.Ws[0][0][0]);
    #pragma unroll
    for (int i = tid; i < HH*FF*FPD/4; i += 256) dst[i] = src[i];
  }
  if (tid < HH*FPD) {
    (&S.as_s[0][0])[tid] = a_self[tid];
    (&S.an_s[0][0])[tid] = a_neigh[tid];
  }
  for (int i = tid; i < 64*(FF/4); i += 256) {
    int nl = i >> 4, q = i & 15;
    float4 v = reinterpret_cast<const float4*>(x + ((size_t)b*NNODE + n0 + nl)*FF)[q];
    S.xs[nl][q*4+0]=v.x; S.xs[nl][q*4+1]=v.y;
    S.xs[nl][q*4+2]=v.z; S.xs[nl][q*4+3]=v.w;
  }
  __syncthreads();

  const int h = tid >> 6, nl = tid & 63;
  float acc[FPD];
  #pragma unroll
  for (int d=0; d<FPD; d++) acc[d] = 0.f;
  #pragma unroll 4
  for (int f=0; f<FF; f++) {
    float xv = S.xs[nl][f];
    const float4* wr = reinterpret_cast<const float4*>(&S.Ws[h][f][0]);
    #pragma unroll
    for (int q=0; q<FPD/4; q++) {
      float4 wv = wr[q];
      acc[q*4+0] += xv*wv.x; acc[q*4+1] += xv*wv.y;
      acc[q*4+2] += xv*wv.z; acc[q*4+3] += xv*wv.w;
    }
  }
  float sv = 0.f, tv = 0.f;
  #pragma unroll
  for (int d=0; d<FPD; d++) { sv += acc[d]*S.as_s[h][d]; tv += acc[d]*S.an_s[h][d]; }

  size_t node = ((size_t)b*HH + h)*NNODE + n0 + nl;
  float4* fd = reinterpret_cast<float4*>(g_feats + node*FPD);
  #pragma unroll
  for (int q=0; q<FPD/4; q++)
    fd[q] = make_float4(acc[q*4+0],acc[q*4+1],acc[q*4+2],acc[q*4+3]);
  g_s[node] = sv;
  g_t[node] = tv;
}

// ==================== kernel 2: tmax per (b,h) ====================
__global__ void __launch_bounds__(256) k_prep() {
  __shared__ float red[256];
  const int bh = blockIdx.x, tid = threadIdx.x;
  float m = -3.0e38f;
  for (int j = tid; j < NNODE; j += 256) m = fmaxf(m, g_t[bh*NNODE + j]);
  red[tid] = m; __syncthreads();
  #pragma unroll
  for (int s = 128; s > 0; s >>= 1) {
    if (tid < s) red[tid] = fmaxf(red[tid], red[tid+s]);
    __syncthreads();
  }
  if (tid == 0) g_tmax[bh] = red[0];
}

// ==================== kernel 3: fused attention ====================
struct SmemA {
  float adj_s[IT][JT+1];     // 8320 B, bank-safe (ii+jj)
  float mask_s[IT][JT+1];    // 8320 B
  float p_s[HH][IT][67];     // 34304 B, pad 67 -> 12*tr bank spread
  float f_s[HH][JT][FPD];    // 32768 B, 16B-aligned rows (offset 50944 % 16 == 0)
  float t_s[HH][JT];
  float sm_s[HH][IT];
  float mm_s[HH][IT];
  float red_l[HH][2][IT];
  float red_p[HH][2][IT];
  int   red_n[HH][2][IT];
  float inv_l[HH][IT];
  int   nzt[HH][IT];
  float elrow[HH][IT];
};

__global__ void __launch_bounds__(256, 2) k_attn(
    const float* __restrict__ adj, const float* __restrict__ msk,
    const float* __restrict__ bias, const float* __restrict__ gamma,
    const float* __restrict__ beta, const float* __restrict__ mean,
    const float* __restrict__ var, float* __restrict__ out) {
  extern __shared__ char raw_a[];
  SmemA& S = *reinterpret_cast<SmemA*>(raw_a);
  const int tid = threadIdx.x;
  const int b = blockIdx.y;
  const int i0 = blockIdx.x * IT;
  const int g = tid >> 6;        // head group
  const int w = tid & 63;        // lane within group

  // ---- prologue: s and row-max bound m = leaky(s + tmax) ----
  if (tid < HH*IT) {
    int gg = tid >> 5, ii = tid & 31;
    float sv = g_s[((size_t)b*HH + gg)*NNODE + i0 + ii];
    S.sm_s[gg][ii] = sv;
    float z = sv + g_tmax[b*HH + gg];
    S.mm_s[gg][ii] = z > 0.f ? z : 0.2f*z;
  }
  __syncthreads();

  // p-gen identity: thread owns (row ii, jj-half) -> register stats
  const int ii = w & 31, half = w >> 5;
  const float my_s = S.sm_s[g][ii];
  const float my_m = S.mm_s[g][ii];
  float lsum = 0.f, psum = 0.f; int nz = 0;

  // GEMM identity: 8x8 thread grid per head, 4x4 micro-tile
  const int tr = w & 7, tc = w >> 3;
  const int r0 = tr * 4, c0 = tc * 4;
  unsigned long long accA[4], accB[4];   // f32x2 packed accumulators
  #pragma unroll
  for (int k=0;k<4;k++) { accA[k]=0ULL; accB[k]=0ULL; }

  const float* adj_b = adj + (size_t)b*NNODE*NNODE + (size_t)i0*NNODE;
  const float* msk_b = msk + (size_t)b*NNODE*NNODE + (size_t)i0*NNODE;

  for (int j0 = 0; j0 < NNODE; j0 += JT) {
    __syncthreads();   // previous GEMM done reading p_s/f_s

    // cooperative loads: adj & mask tiles (coalesced, once per block-tile)
    {
      int r = tid >> 3, q = tid & 7;
      const float4* ga = reinterpret_cast<const float4*>(adj_b + (size_t)r*NNODE + j0);
      const float4* gm = reinterpret_cast<const float4*>(msk_b + (size_t)r*NNODE + j0);
      float4 a0 = ga[q*2], a1 = ga[q*2+1];
      float4 m0 = gm[q*2], m1 = gm[q*2+1];
      int c = q*8;
      S.adj_s[r][c+0]=a0.x; S.adj_s[r][c+1]=a0.y; S.adj_s[r][c+2]=a0.z; S.adj_s[r][c+3]=a0.w;
      S.adj_s[r][c+4]=a1.x; S.adj_s[r][c+5]=a1.y; S.adj_s[r][c+6]=a1.z; S.adj_s[r][c+7]=a1.w;
      S.mask_s[r][c+0]=m0.x; S.mask_s[r][c+1]=m0.y; S.mask_s[r][c+2]=m0.z; S.mask_s[r][c+3]=m0.w;
      S.mask_s[r][c+4]=m1.x; S.mask_s[r][c+5]=m1.y; S.mask_s[r][c+6]=m1.z; S.mask_s[r][c+7]=m1.w;
    }
    // feats tile: group g loads its own head's rows (thread w -> row jj=w)
    {
      const float4* gf = reinterpret_cast<const float4*>(
          g_feats + (((size_t)b*HH + g)*NNODE + j0 + w)*FPD);
      float4* dst = reinterpret_cast<float4*>(&S.f_s[g][w][0]);
      #pragma unroll
      for (int q=0; q<FPD/4; q++) dst[q] = gf[q];
    }
    S.t_s[g][w] = g_t[((size_t)b*HH + g)*NNODE + j0 + w];
    __syncthreads();

    // ---- p-gen: e = exp(leaky(s+t)+mask-m); p = e*adj ----
    #pragma unroll 4
    for (int st = 0; st < 32; st++) {
      int jj = half*32 + st;
      float z = my_s + S.t_s[g][jj];
      z = z > 0.f ? z : 0.2f*z;
      float e = __expf(z + S.mask_s[ii][jj] - my_m);
      float pe = e * S.adj_s[ii][jj];
      lsum += e; psum += pe; nz += (pe != 0.f);
      S.p_s[g][ii][jj] = pe;
    }
    __syncthreads();

    // ---- GEMM: acc[4x4] += p[32x64] @ f[64x32] via fma.rn.f32x2 ----
    #pragma unroll 16
    for (int jj = 0; jj < JT; jj++) {
      const ulonglong2 fv = *reinterpret_cast<const ulonglong2*>(&S.f_s[g][jj][c0]);
      #pragma unroll
      for (int k=0; k<4; k++) {
        float pk = S.p_s[g][r0+k][jj];
        unsigned long long pp;
        asm("mov.b64 %0, {%1, %1};" : "=l"(pp) : "f"(pk));
        asm("fma.rn.f32x2 %0, %1, %2, %3;" : "=l"(accA[k]) : "l"(pp), "l"(fv.x), "l"(accA[k]));
        asm("fma.rn.f32x2 %0, %1, %2, %3;" : "=l"(accB[k]) : "l"(pp), "l"(fv.y), "l"(accB[k]));
      }
    }
  }

  // ---- combine per-row stats ----
  S.red_l[g][half][ii] = lsum;
  S.red_p[g][half][ii] = psum;
  S.red_n[g][half][ii] = nz;
  __syncthreads();
  if (w < IT) {
    float lt = S.red_l[g][0][w] + S.red_l[g][1][w];
    float pt = S.red_p[g][0][w] + S.red_p[g][1][w];
    int   nt = S.red_n[g][0][w] + S.red_n[g][1][w];
    float il = 1.f / lt;
    S.inv_l[g][w] = il;
    S.nzt[g][w]   = nt;
    S.elrow[g][w] = pt * il;
  }
  __syncthreads();

  // ---- block loss partials (deterministic; final reduce in k_final) ----
  if (tid < IT) {
    float el = 0.f; int ul = 0;
    #pragma unroll
    for (int g2=0; g2<HH; g2++) { el += S.elrow[g2][tid]; ul += S.nzt[g2][tid] - S.nzt[0][tid]; }
    #pragma unroll
    for (int off=16; off>0; off>>=1) {
      el += __shfl_down_sync(0xffffffffu, el, off);
      ul += __shfl_down_sync(0xffffffffu, ul, off);
    }
    if (tid == 0) {
      int blk = blockIdx.y * gridDim.x + blockIdx.x;
      g_losse[blk] = el * (1.f/NNODE);
      g_lossu[blk] = (float)ul * (1.f/NNODE);
    }
  }

  // ---- epilogue: normalize, +bias, batchnorm(inference), relu, store ----
  {
    const int ch0 = g*FPD + c0;
    float sc[4], sh[4], bs[4];
    #pragma unroll
    for (int m2=0; m2<4; m2++) {
      float va = var[ch0+m2];
      sc[m2] = gamma[ch0+m2] * rsqrtf(va + 1e-3f);
      sh[m2] = beta[ch0+m2] - mean[ch0+m2]*sc[m2];
      bs[m2] = bias[ch0+m2];
    }
    #pragma unroll
    for (int k=0; k<4; k++) {
      int r = r0 + k;
      float il = S.inv_l[g][r];
      float v0,v1,v2,v3;
      asm("mov.b64 {%0, %1}, %2;" : "=f"(v0), "=f"(v1) : "l"(accA[k]));
      asm("mov.b64 {%0, %1}, %2;" : "=f"(v2), "=f"(v3) : "l"(accB[k]));
      float4 o;
      o.x = fmaxf((v0*il + bs[0])*sc[0] + sh[0], 0.f);
      o.y = fmaxf((v1*il + bs[1])*sc[1] + sh[1], 0.f);
      o.z = fmaxf((v2*il + bs[2])*sc[2] + sh[2], 0.f);
      o.w = fmaxf((v3*il + bs[3])*sc[3] + sh[3], 0.f);
      *reinterpret_cast<float4*>(out + ((size_t)(b*NNODE + i0 + r))*CH + ch0) = o;
    }
  }
}

// ==================== kernel 4: deterministic loss reduce ====================
__global__ void __launch_bounds__(256) k_final(float* __restrict__ out) {
  __shared__ float ru[256], re[256];
  const int tid = threadIdx.x;
  ru[tid] = g_lossu[tid];
  re[tid] = g_losse[tid];
  __syncthreads();
  #pragma unroll
  for (int s=128; s>0; s>>=1) {
    if (tid < s) { ru[tid] += ru[tid+s]; re[tid] += re[tid+s]; }
    __syncthreads();
  }
  if (tid == 0) { out[OUT_MAIN + 0] = ru[0]; out[OUT_MAIN + 1] = re[0]; }
}

// ==================== launch ====================
extern "C" void kernel_launch(void* const* d_in, const int* in_sizes, int n_in,
                              void* d_out, int out_size) {
  const float* x       = (const float*)d_in[0];
  const float* adj     = (const float*)d_in[1];
  const float* msk     = (const float*)d_in[2];
  const float* W       = (const float*)d_in[3];
  const float* a_self  = (const float*)d_in[4];
  const float* a_neigh = (const float*)d_in[5];
  const float* bias    = (const float*)d_in[6];
  const float* gamma   = (const float*)d_in[7];
  const float* beta    = (const float*)d_in[8];
  const float* mean    = (const float*)d_in[9];
  const float* var     = (const float*)d_in[10];
  float* out = (float*)d_out;

  cudaFuncSetAttribute(k_feats, cudaFuncAttributeMaxDynamicSharedMemorySize, (int)sizeof(SmemF));
  cudaFuncSetAttribute(k_attn,  cudaFuncAttributeMaxDynamicSharedMemorySize, (int)sizeof(SmemA));

  k_feats<<<dim3(NNODE/64, BB), 256, sizeof(SmemF)>>>(x, W, a_self, a_neigh);
  k_prep<<<BB*HH, 256>>>();
  k_attn<<<dim3(NNODE/IT, BB), 256, sizeof(SmemA)>>>(adj, msk, bias, gamma, beta, mean, var, out);
  k_final<<<1, 256>>>(out);
}

// round 3
// speedup vs baseline: 1.1626x; 1.1626x over previous
#include <cuda_runtime.h>
#include <cstdint>

#define BB 4
#define NNODE 2048
#define FF 64
#define FPD 32
#define HH 4
#define IT 64          // rows per block
#define JT 32          // j tile
#define CH (HH*FPD)    // 128
#define OUT_MAIN (BB*NNODE*CH)   // 1048576
#define NBLK (BB*(NNODE/IT))     // 128

// ---------------- device scratch ----------------
__device__ float g_feats[(size_t)BB*HH*NNODE*FPD];
__device__ float g_s[BB*HH*NNODE];
__device__ float g_t[BB*HH*NNODE];
__device__ float g_tmax[BB*HH];
__device__ float g_lossu[NBLK];
__device__ float g_losse[NBLK];
__device__ int   g_cnt = 0;

// ==================== kernel 1: feats = x@W, s, t ====================
struct SmemF {
  float Ws[HH][FF][FPD];
  float xs[64][FF+1];
  float as_s[HH][FPD];
  float an_s[HH][FPD];
};

__global__ void __launch_bounds__(256) k_feats(const float* __restrict__ x,
    const float* __restrict__ W, const float* __restrict__ a_self,
    const float* __restrict__ a_neigh) {
  extern __shared__ char raw_f[];
  SmemF& S = *reinterpret_cast<SmemF*>(raw_f);
  const int tid = threadIdx.x;
  const int b = blockIdx.y;
  const int n0 = blockIdx.x * 64;

  {
    const float4* src = reinterpret_cast<const float4*>(W);
    float4* dst = reinterpret_cast<float4*>(&S.Ws[0][0][0]);
    #pragma unroll
    for (int i = tid; i < HH*FF*FPD/4; i += 256) dst[i] = src[i];
  }
  if (tid < HH*FPD) {
    (&S.as_s[0][0])[tid] = a_self[tid];
    (&S.an_s[0][0])[tid] = a_neigh[tid];
  }
  for (int i = tid; i < 64*(FF/4); i += 256) {
    int nl = i >> 4, q = i & 15;
    float4 v = reinterpret_cast<const float4*>(x + ((size_t)b*NNODE + n0 + nl)*FF)[q];
    S.xs[nl][q*4+0]=v.x; S.xs[nl][q*4+1]=v.y;
    S.xs[nl][q*4+2]=v.z; S.xs[nl][q*4+3]=v.w;
  }
  __syncthreads();

  const int h = tid >> 6, nl = tid & 63;
  float acc[FPD];
  #pragma unroll
  for (int d=0; d<FPD; d++) acc[d] = 0.f;
  #pragma unroll 4
  for (int f=0; f<FF; f++) {
    float xv = S.xs[nl][f];
    const float4* wr = reinterpret_cast<const float4*>(&S.Ws[h][f][0]);
    #pragma unroll
    for (int q=0; q<FPD/4; q++) {
      float4 wv = wr[q];
      acc[q*4+0] += xv*wv.x; acc[q*4+1] += xv*wv.y;
      acc[q*4+2] += xv*wv.z; acc[q*4+3] += xv*wv.w;
    }
  }
  float sv = 0.f, tv = 0.f;
  #pragma unroll
  for (int d=0; d<FPD; d++) { sv += acc[d]*S.as_s[h][d]; tv += acc[d]*S.an_s[h][d]; }

  size_t node = ((size_t)b*HH + h)*NNODE + n0 + nl;
  float4* fd = reinterpret_cast<float4*>(g_feats + node*FPD);
  #pragma unroll
  for (int q=0; q<FPD/4; q++)
    fd[q] = make_float4(acc[q*4+0],acc[q*4+1],acc[q*4+2],acc[q*4+3]);
  g_s[node] = sv;
  g_t[node] = tv;
}

// ==================== kernel 2: tmax per (b,h) ====================
__global__ void __launch_bounds__(256) k_prep() {
  __shared__ float red[256];
  const int bh = blockIdx.x, tid = threadIdx.x;
  float m = -3.0e38f;
  for (int j = tid; j < NNODE; j += 256) m = fmaxf(m, g_t[bh*NNODE + j]);
  red[tid] = m; __syncthreads();
  #pragma unroll
  for (int s = 128; s > 0; s >>= 1) {
    if (tid < s) red[tid] = fmaxf(red[tid], red[tid+s]);
    __syncthreads();
  }
  if (tid == 0) g_tmax[bh] = red[0];
}

// ==================== kernel 3: fused attention ====================
struct SmemA {
  float adj_s[IT][36];      // 9216 B, float4-friendly pad, conflict-free
  float mask_s[IT][36];     // 9216 B
  float pT[HH][JT][68];     // 34816 B, transposed p: [jj][ii], 16B-aligned rows
  float f_s[HH][JT][FPD];   // 16384 B
  float t_s[HH][JT];        // 512 B
  float inv_l[HH][IT];      // 1024 B
  float red_e[256];         // 1024 B
  int   red_u[256];         // 1024 B
};                          // ~73 KB

__global__ void __launch_bounds__(256) k_attn(
    const float* __restrict__ adj, const float* __restrict__ msk,
    const float* __restrict__ bias, const float* __restrict__ gamma,
    const float* __restrict__ beta, const float* __restrict__ mean,
    const float* __restrict__ var, float* __restrict__ out) {
  extern __shared__ char raw_a[];
  SmemA& S = *reinterpret_cast<SmemA*>(raw_a);
  __shared__ int lastflag;
  const int tid = threadIdx.x;
  const int b = blockIdx.y;
  const int i0 = blockIdx.x * IT;
  const int g = tid >> 6;        // head
  const int w = tid & 63;        // lane within head group

  // p-gen identity: thread owns row (i0+w) of head g for ALL j.
  const size_t bh = (size_t)b*HH + g;
  const float my_s = g_s[bh*NNODE + i0 + w];
  float zb = my_s + g_tmax[bh];
  const float my_m = fmaxf(zb, 0.2f*zb);       // leaky is monotone; mask==const-add
  float lsum = 0.f, psum = 0.f; int nz = 0, dg = 0;

  // GEMM identity: 8x8 thread grid per head, 8 rows x 4 cols micro-tile
  const int r0 = (w >> 3) * 8, c0 = (w & 7) * 4;
  unsigned long long acc[4][4];   // [row-pair][col], f32x2 packed
  #pragma unroll
  for (int rp=0; rp<4; rp++)
    #pragma unroll
    for (int c=0; c<4; c++) acc[rp][c] = 0ULL;

  const float* adj_b = adj + (size_t)b*NNODE*NNODE + (size_t)i0*NNODE;
  const float* msk_b = msk + (size_t)b*NNODE*NNODE + (size_t)i0*NNODE;
  const float* fbase = g_feats + bh*NNODE*FPD;
  const float* tbase = g_t + bh*NNODE;

  for (int j0 = 0; j0 < NNODE; j0 += JT) {
    __syncthreads();   // prior p-gen done with adj/mask, prior GEMM done with pT/f

    // ---- cooperative tile loads ----
    #pragma unroll
    for (int it2 = 0; it2 < 2; it2++) {
      int idx = tid + it2*256;
      int r = idx >> 3, q = idx & 7;
      float4 a = reinterpret_cast<const float4*>(adj_b + (size_t)r*NNODE + j0)[q];
      float4 m = reinterpret_cast<const float4*>(msk_b + (size_t)r*NNODE + j0)[q];
      *reinterpret_cast<float4*>(&S.adj_s[r][q*4])  = a;
      *reinterpret_cast<float4*>(&S.mask_s[r][q*4]) = m;
    }
    {
      int jj = w & 31, hf = w >> 5;
      const float4* gf = reinterpret_cast<const float4*>(fbase + (size_t)(j0 + jj)*FPD);
      float4* df = reinterpret_cast<float4*>(&S.f_s[g][jj][0]);
      #pragma unroll
      for (int q=0; q<4; q++) df[hf*4+q] = gf[hf*4+q];
      if (w < JT) S.t_s[g][w] = tbase[j0 + w];
    }
    __syncthreads();

    // ---- p-gen: row w, 32 columns, float4 loads, transposed stores ----
    #pragma unroll
    for (int q = 0; q < 8; q++) {
      float4 tv = *reinterpret_cast<const float4*>(&S.t_s[g][q*4]);
      float4 mk = *reinterpret_cast<const float4*>(&S.mask_s[w][q*4]);
      float4 av = *reinterpret_cast<const float4*>(&S.adj_s[w][q*4]);
      float tt[4] = {tv.x, tv.y, tv.z, tv.w};
      float mmk[4] = {mk.x, mk.y, mk.z, mk.w};
      float aa[4] = {av.x, av.y, av.z, av.w};
      #pragma unroll
      for (int l = 0; l < 4; l++) {
        float z = my_s + tt[l];
        z = fmaxf(z, 0.2f*z);                  // LeakyReLU(0.2)
        float e = __expf(z + mmk[l] - my_m);
        float pe = e * aa[l];
        lsum += e; psum += pe;
        nz += (pe != 0.f); dg += (aa[l] != 0.f);
        S.pT[g][q*4 + l][w] = pe;
      }
    }
    __syncthreads();

    // ---- GEMM: acc += pT[jj][64-rows] x f[jj][32-cols], f32x2 packed ----
    #pragma unroll 8
    for (int jj = 0; jj < JT; jj++) {
      ulonglong2 pa = *reinterpret_cast<const ulonglong2*>(&S.pT[g][jj][r0]);
      ulonglong2 pb = *reinterpret_cast<const ulonglong2*>(&S.pT[g][jj][r0+4]);
      float4 fv = *reinterpret_cast<const float4*>(&S.f_s[g][jj][c0]);
      unsigned long long fd0, fd1, fd2, fd3;
      asm("mov.b64 %0, {%1, %1};" : "=l"(fd0) : "f"(fv.x));
      asm("mov.b64 %0, {%1, %1};" : "=l"(fd1) : "f"(fv.y));
      asm("mov.b64 %0, {%1, %1};" : "=l"(fd2) : "f"(fv.z));
      asm("mov.b64 %0, {%1, %1};" : "=l"(fd3) : "f"(fv.w));
      unsigned long long pp[4] = {pa.x, pa.y, pb.x, pb.y};
      #pragma unroll
      for (int rp = 0; rp < 4; rp++) {
        asm("fma.rn.f32x2 %0, %1, %2, %3;" : "=l"(acc[rp][0]) : "l"(pp[rp]), "l"(fd0), "l"(acc[rp][0]));
        asm("fma.rn.f32x2 %0, %1, %2, %3;" : "=l"(acc[rp][1]) : "l"(pp[rp]), "l"(fd1), "l"(acc[rp][1]));
        asm("fma.rn.f32x2 %0, %1, %2, %3;" : "=l"(acc[rp][2]) : "l"(pp[rp]), "l"(fd2), "l"(acc[rp][2]));
        asm("fma.rn.f32x2 %0, %1, %2, %3;" : "=l"(acc[rp][3]) : "l"(pp[rp]), "l"(fd3), "l"(acc[rp][3]));
      }
    }
  }

  // ---- row stats + block loss partials ----
  float il = 1.f / lsum;
  S.inv_l[g][w] = il;
  S.red_e[tid] = psum * il;
  S.red_u[tid] = nz - dg;
  __syncthreads();
  #pragma unroll
  for (int s2 = 128; s2 > 0; s2 >>= 1) {
    if (tid < s2) { S.red_e[tid] += S.red_e[tid+s2]; S.red_u[tid] += S.red_u[tid+s2]; }
    __syncthreads();
  }
  if (tid == 0) {
    int blk = blockIdx.y * gridDim.x + blockIdx.x;
    g_losse[blk] = S.red_e[0];
    g_lossu[blk] = (float)S.red_u[0];
  }

  // ---- epilogue: normalize, +bias, inference BN, relu, store ----
  {
    const int ch0 = g*FPD + c0;
    float sc[4], sh[4], bs[4];
    #pragma unroll
    for (int m2=0; m2<4; m2++) {
      float va = var[ch0+m2];
      sc[m2] = gamma[ch0+m2] * rsqrtf(va + 1e-3f);
      sh[m2] = beta[ch0+m2] - mean[ch0+m2]*sc[m2];
      bs[m2] = bias[ch0+m2];
    }
    #pragma unroll
    for (int rp = 0; rp < 4; rp++) {
      float lo[4], hi[4];
      #pragma unroll
      for (int c = 0; c < 4; c++)
        asm("mov.b64 {%0, %1}, %2;" : "=f"(lo[c]), "=f"(hi[c]) : "l"(acc[rp][c]));
      int re = r0 + 2*rp, ro = re + 1;
      float ilE = S.inv_l[g][re], ilO = S.inv_l[g][ro];
      float4 oe, oo;
      oe.x = fmaxf((lo[0]*ilE + bs[0])*sc[0] + sh[0], 0.f);
      oe.y = fmaxf((lo[1]*ilE + bs[1])*sc[1] + sh[1], 0.f);
      oe.z = fmaxf((lo[2]*ilE + bs[2])*sc[2] + sh[2], 0.f);
      oe.w = fmaxf((lo[3]*ilE + bs[3])*sc[3] + sh[3], 0.f);
      oo.x = fmaxf((hi[0]*ilO + bs[0])*sc[0] + sh[0], 0.f);
      oo.y = fmaxf((hi[1]*ilO + bs[1])*sc[1] + sh[1], 0.f);
      oo.z = fmaxf((hi[2]*ilO + bs[2])*sc[2] + sh[2], 0.f);
      oo.w = fmaxf((hi[3]*ilO + bs[3])*sc[3] + sh[3], 0.f);
      *reinterpret_cast<float4*>(out + ((size_t)(b*NNODE + i0 + re))*CH + ch0) = oe;
      *reinterpret_cast<float4*>(out + ((size_t)(b*NNODE + i0 + ro))*CH + ch0) = oo;
    }
  }

  // ---- deterministic last-block loss finalize ----
  if (tid == 0) {
    __threadfence();
    int old = atomicAdd(&g_cnt, 1);
    lastflag = (old == NBLK - 1);
  }
  __syncthreads();
  if (lastflag && tid == 0) {
    __threadfence();
    float su = 0.f, se = 0.f;
    #pragma unroll 8
    for (int i = 0; i < NBLK; i++) { su += g_lossu[i]; se += g_losse[i]; }
    out[OUT_MAIN + 0] = su * (1.f/NNODE);
    out[OUT_MAIN + 1] = se * (1.f/NNODE);
    g_cnt = 0;
  }
}

// ==================== launch ====================
extern "C" void kernel_launch(void* const* d_in, const int* in_sizes, int n_in,
                              void* d_out, int out_size) {
  const float* x       = (const float*)d_in[0];
  const float* adj     = (const float*)d_in[1];
  const float* msk     = (const float*)d_in[2];
  const float* W       = (const float*)d_in[3];
  const float* a_self  = (const float*)d_in[4];
  const float* a_neigh = (const float*)d_in[5];
  const float* bias    = (const float*)d_in[6];
  const float* gamma   = (const float*)d_in[7];
  const float* beta    = (const float*)d_in[8];
  const float* mean    = (const float*)d_in[9];
  const float* var     = (const float*)d_in[10];
  float* out = (float*)d_out;

  cudaFuncSetAttribute(k_feats, cudaFuncAttributeMaxDynamicSharedMemorySize, (int)sizeof(SmemF));
  cudaFuncSetAttribute(k_attn,  cudaFuncAttributeMaxDynamicSharedMemorySize, (int)sizeof(SmemA));

  k_feats<<<dim3(NNODE/64, BB), 256, sizeof(SmemF)>>>(x, W, a_self, a_neigh);
  k_prep<<<BB*HH, 256>>>();
  k_attn<<<dim3(NNODE/IT, BB), 256, sizeof(SmemA)>>>(adj, msk, bias, gamma, beta, mean, var, out);
}

// round 4
// speedup vs baseline: 1.1635x; 1.0007x over previous
#include <cuda_runtime.h>
#include <cstdint>

#define BB 4
#define NNODE 2048
#define FF 64
#define FPD 32
#define HH 4
#define IT 64          // rows per block
#define JT 32          // j tile
#define CH (HH*FPD)    // 128
#define OUT_MAIN (BB*NNODE*CH)   // 1048576
#define NBLK (BB*(NNODE/IT))     // 128

// ---------------- device scratch ----------------
__device__ float g_feats[(size_t)BB*HH*NNODE*FPD];
__device__ float g_s[BB*HH*NNODE];
__device__ float g_t[BB*HH*NNODE];
__device__ float g_tmax[BB*HH];
__device__ float g_lossu[NBLK];
__device__ float g_losse[NBLK];
__device__ int   g_cnt = 0;

// ==================== kernel 1: feats = x@W, s, t ====================
struct SmemF {
  float Ws[HH][FF][FPD];
  float xs[64][FF+1];
  float as_s[HH][FPD];
  float an_s[HH][FPD];
};

__global__ void __launch_bounds__(256) k_feats(const float* __restrict__ x,
    const float* __restrict__ W, const float* __restrict__ a_self,
    const float* __restrict__ a_neigh) {
  extern __shared__ char raw_f[];
  SmemF& S = *reinterpret_cast<SmemF*>(raw_f);
  const int tid = threadIdx.x;
  const int b = blockIdx.y;
  const int n0 = blockIdx.x * 64;

  {
    const float4* src = reinterpret_cast<const float4*>(W);
    float4* dst = reinterpret_cast<float4*>(&S.Ws[0][0][0]);
    #pragma unroll
    for (int i = tid; i < HH*FF*FPD/4; i += 256) dst[i] = src[i];
  }
  if (tid < HH*FPD) {
    (&S.as_s[0][0])[tid] = a_self[tid];
    (&S.an_s[0][0])[tid] = a_neigh[tid];
  }
  for (int i = tid; i < 64*(FF/4); i += 256) {
    int nl = i >> 4, q = i & 15;
    float4 v = reinterpret_cast<const float4*>(x + ((size_t)b*NNODE + n0 + nl)*FF)[q];
    S.xs[nl][q*4+0]=v.x; S.xs[nl][q*4+1]=v.y;
    S.xs[nl][q*4+2]=v.z; S.xs[nl][q*4+3]=v.w;
  }
  __syncthreads();

  const int h = tid >> 6, nl = tid & 63;
  float acc[FPD];
  #pragma unroll
  for (int d=0; d<FPD; d++) acc[d] = 0.f;
  #pragma unroll 4
  for (int f=0; f<FF; f++) {
    float xv = S.xs[nl][f];
    const float4* wr = reinterpret_cast<const float4*>(&S.Ws[h][f][0]);
    #pragma unroll
    for (int q=0; q<FPD/4; q++) {
      float4 wv = wr[q];
      acc[q*4+0] += xv*wv.x; acc[q*4+1] += xv*wv.y;
      acc[q*4+2] += xv*wv.z; acc[q*4+3] += xv*wv.w;
    }
  }
  float sv = 0.f, tv = 0.f;
  #pragma unroll
  for (int d=0; d<FPD; d++) { sv += acc[d]*S.as_s[h][d]; tv += acc[d]*S.an_s[h][d]; }

  size_t node = ((size_t)b*HH + h)*NNODE + n0 + nl;
  float4* fd = reinterpret_cast<float4*>(g_feats + node*FPD);
  #pragma unroll
  for (int q=0; q<FPD/4; q++)
    fd[q] = make_float4(acc[q*4+0],acc[q*4+1],acc[q*4+2],acc[q*4+3]);
  g_s[node] = sv;
  g_t[node] = tv;
}

// ==================== kernel 2: tmax per (b,h) ====================
__global__ void __launch_bounds__(256) k_prep() {
  __shared__ float red[256];
  const int bh = blockIdx.x, tid = threadIdx.x;
  float m = -3.0e38f;
  for (int j = tid; j < NNODE; j += 256) m = fmaxf(m, g_t[bh*NNODE + j]);
  red[tid] = m; __syncthreads();
  #pragma unroll
  for (int s = 128; s > 0; s >>= 1) {
    if (tid < s) red[tid] = fmaxf(red[tid], red[tid+s]);
    __syncthreads();
  }
  if (tid == 0) g_tmax[bh] = red[0];
}

// ==================== kernel 3: fused attention ====================
struct SmemA {
  float adj_s[IT][36];      // 9216 B, float4-friendly pad, conflict-free
  float mask_s[IT][36];     // 9216 B
  float pT[HH][JT][68];     // 34816 B, transposed p: [jj][ii], 16B-aligned rows
  float f_s[HH][JT][FPD];   // 16384 B
  float t_s[HH][JT];        // 512 B
  float inv_l[HH][IT];      // 1024 B
  float red_e[256];         // 1024 B
  int   red_u[256];         // 1024 B
};                          // ~73 KB

__global__ void __launch_bounds__(256) k_attn(
    const float* __restrict__ adj, const float* __restrict__ msk,
    const float* __restrict__ bias, const float* __restrict__ gamma,
    const float* __restrict__ beta, const float* __restrict__ mean,
    const float* __restrict__ var, float* __restrict__ out) {
  extern __shared__ char raw_a[];
  SmemA& S = *reinterpret_cast<SmemA*>(raw_a);
  __shared__ int lastflag;
  const int tid = threadIdx.x;
  const int b = blockIdx.y;
  const int i0 = blockIdx.x * IT;
  const int g = tid >> 6;        // head
  const int w = tid & 63;        // lane within head group

  // p-gen identity: thread owns row (i0+w) of head g for ALL j.
  const size_t bh = (size_t)b*HH + g;
  const float my_s = g_s[bh*NNODE + i0 + w];
  float zb = my_s + g_tmax[bh];
  const float my_m = fmaxf(zb, 0.2f*zb);       // leaky is monotone; mask==const-add
  float lsum = 0.f, psum = 0.f; int nz = 0, dg = 0;

  // GEMM identity: 8x8 thread grid per head, 8 rows x 4 cols micro-tile
  const int r0 = (w >> 3) * 8, c0 = (w & 7) * 4;
  unsigned long long acc[4][4];   // [row-pair][col], f32x2 packed
  #pragma unroll
  for (int rp=0; rp<4; rp++)
    #pragma unroll
    for (int c=0; c<4; c++) acc[rp][c] = 0ULL;

  const float* adj_b = adj + (size_t)b*NNODE*NNODE + (size_t)i0*NNODE;
  const float* msk_b = msk + (size_t)b*NNODE*NNODE + (size_t)i0*NNODE;
  const float* fbase = g_feats + bh*NNODE*FPD;
  const float* tbase = g_t + bh*NNODE;

  for (int j0 = 0; j0 < NNODE; j0 += JT) {
    __syncthreads();   // prior p-gen done with adj/mask, prior GEMM done with pT/f

    // ---- cooperative tile loads ----
    #pragma unroll
    for (int it2 = 0; it2 < 2; it2++) {
      int idx = tid + it2*256;
      int r = idx >> 3, q = idx & 7;
      float4 a = reinterpret_cast<const float4*>(adj_b + (size_t)r*NNODE + j0)[q];
      float4 m = reinterpret_cast<const float4*>(msk_b + (size_t)r*NNODE + j0)[q];
      *reinterpret_cast<float4*>(&S.adj_s[r][q*4])  = a;
      *reinterpret_cast<float4*>(&S.mask_s[r][q*4]) = m;
    }
    {
      int jj = w & 31, hf = w >> 5;
      const float4* gf = reinterpret_cast<const float4*>(fbase + (size_t)(j0 + jj)*FPD);
      float4* df = reinterpret_cast<float4*>(&S.f_s[g][jj][0]);
      #pragma unroll
      for (int q=0; q<4; q++) df[hf*4+q] = gf[hf*4+q];
      if (w < JT) S.t_s[g][w] = tbase[j0 + w];
    }
    __syncthreads();

    // ---- p-gen: row w, 32 columns, float4 loads, transposed stores ----
    #pragma unroll
    for (int q = 0; q < 8; q++) {
      float4 tv = *reinterpret_cast<const float4*>(&S.t_s[g][q*4]);
      float4 mk = *reinterpret_cast<const float4*>(&S.mask_s[w][q*4]);
      float4 av = *reinterpret_cast<const float4*>(&S.adj_s[w][q*4]);
      float tt[4] = {tv.x, tv.y, tv.z, tv.w};
      float mmk[4] = {mk.x, mk.y, mk.z, mk.w};
      float aa[4] = {av.x, av.y, av.z, av.w};
      #pragma unroll
      for (int l = 0; l < 4; l++) {
        float z = my_s + tt[l];
        z = fmaxf(z, 0.2f*z);                  // LeakyReLU(0.2)
        float e = __expf(z + mmk[l] - my_m);
        float pe = e * aa[l];
        lsum += e; psum += pe;
        nz += (pe != 0.f); dg += (aa[l] != 0.f);
        S.pT[g][q*4 + l][w] = pe;
      }
    }
    __syncthreads();

    // ---- GEMM: acc += pT[jj][64-rows] x f[jj][32-cols], f32x2 packed ----
    #pragma unroll 8
    for (int jj = 0; jj < JT; jj++) {
      ulonglong2 pa = *reinterpret_cast<const ulonglong2*>(&S.pT[g][jj][r0]);
      ulonglong2 pb = *reinterpret_cast<const ulonglong2*>(&S.pT[g][jj][r0+4]);
      float4 fv = *reinterpret_cast<const float4*>(&S.f_s[g][jj][c0]);
      unsigned long long fd0, fd1, fd2, fd3;
      asm("mov.b64 %0, {%1, %1};" : "=l"(fd0) : "f"(fv.x));
      asm("mov.b64 %0, {%1, %1};" : "=l"(fd1) : "f"(fv.y));
      asm("mov.b64 %0, {%1, %1};" : "=l"(fd2) : "f"(fv.z));
      asm("mov.b64 %0, {%1, %1};" : "=l"(fd3) : "f"(fv.w));
      unsigned long long pp[4] = {pa.x, pa.y, pb.x, pb.y};
      #pragma unroll
      for (int rp = 0; rp < 4; rp++) {
        asm("fma.rn.f32x2 %0, %1, %2, %3;" : "=l"(acc[rp][0]) : "l"(pp[rp]), "l"(fd0), "l"(acc[rp][0]));
        asm("fma.rn.f32x2 %0, %1, %2, %3;" : "=l"(acc[rp][1]) : "l"(pp[rp]), "l"(fd1), "l"(acc[rp][1]));
        asm("fma.rn.f32x2 %0, %1, %2, %3;" : "=l"(acc[rp][2]) : "l"(pp[rp]), "l"(fd2), "l"(acc[rp][2]));
        asm("fma.rn.f32x2 %0, %1, %2, %3;" : "=l"(acc[rp][3]) : "l"(pp[rp]), "l"(fd3), "l"(acc[rp][3]));
      }
    }
  }

  // ---- row stats + block loss partials ----
  float il = 1.f / lsum;
  S.inv_l[g][w] = il;
  S.red_e[tid] = psum * il;
  S.red_u[tid] = nz - dg;
  __syncthreads();
  #pragma unroll
  for (int s2 = 128; s2 > 0; s2 >>= 1) {
    if (tid < s2) { S.red_e[tid] += S.red_e[tid+s2]; S.red_u[tid] += S.red_u[tid+s2]; }
    __syncthreads();
  }
  if (tid == 0) {
    int blk = blockIdx.y * gridDim.x + blockIdx.x;
    g_losse[blk] = S.red_e[0];
    g_lossu[blk] = (float)S.red_u[0];
  }

  // ---- epilogue: normalize, +bias, inference BN, relu, store ----
  {
    const int ch0 = g*FPD + c0;
    float sc[4], sh[4], bs[4];
    #pragma unroll
    for (int m2=0; m2<4; m2++) {
      float va = var[ch0+m2];
      sc[m2] = gamma[ch0+m2] * rsqrtf(va + 1e-3f);
      sh[m2] = beta[ch0+m2] - mean[ch0+m2]*sc[m2];
      bs[m2] = bias[ch0+m2];
    }
    #pragma unroll
    for (int rp = 0; rp < 4; rp++) {
      float lo[4], hi[4];
      #pragma unroll
      for (int c = 0; c < 4; c++)
        asm("mov.b64 {%0, %1}, %2;" : "=f"(lo[c]), "=f"(hi[c]) : "l"(acc[rp][c]));
      int re = r0 + 2*rp, ro = re + 1;
      float ilE = S.inv_l[g][re], ilO = S.inv_l[g][ro];
      float4 oe, oo;
      oe.x = fmaxf((lo[0]*ilE + bs[0])*sc[0] + sh[0], 0.f);
      oe.y = fmaxf((lo[1]*ilE + bs[1])*sc[1] + sh[1], 0.f);
      oe.z = fmaxf((lo[2]*ilE + bs[2])*sc[2] + sh[2], 0.f);
      oe.w = fmaxf((lo[3]*ilE + bs[3])*sc[3] + sh[3], 0.f);
      oo.x = fmaxf((hi[0]*ilO + bs[0])*sc[0] + sh[0], 0.f);
      oo.y = fmaxf((hi[1]*ilO + bs[1])*sc[1] + sh[1], 0.f);
      oo.z = fmaxf((hi[2]*ilO + bs[2])*sc[2] + sh[2], 0.f);
      oo.w = fmaxf((hi[3]*ilO + bs[3])*sc[3] + sh[3], 0.f);
      *reinterpret_cast<float4*>(out + ((size_t)(b*NNODE + i0 + re))*CH + ch0) = oe;
      *reinterpret_cast<float4*>(out + ((size_t)(b*NNODE + i0 + ro))*CH + ch0) = oo;
    }
  }

  // ---- deterministic last-block loss finalize ----
  if (tid == 0) {
    __threadfence();
    int old = atomicAdd(&g_cnt, 1);
    lastflag = (old == NBLK - 1);
  }
  __syncthreads();
  if (lastflag && tid == 0) {
    __threadfence();
    float su = 0.f, se = 0.f;
    #pragma unroll 8
    for (int i = 0; i < NBLK; i++) { su += g_lossu[i]; se += g_losse[i]; }
    out[OUT_MAIN + 0] = su * (1.f/NNODE);
    out[OUT_MAIN + 1] = se * (1.f/NNODE);
    g_cnt = 0;
  }
}

// ==================== launch ====================
extern "C" void kernel_launch(void* const* d_in, const int* in_sizes, int n_in,
                              void* d_out, int out_size) {
  const float* x       = (const float*)d_in[0];
  const float* adj     = (const float*)d_in[1];
  const float* msk     = (const float*)d_in[2];
  const float* W       = (const float*)d_in[3];
  const float* a_self  = (const float*)d_in[4];
  const float* a_neigh = (const float*)d_in[5];
  const float* bias    = (const float*)d_in[6];
  const float* gamma   = (const float*)d_in[7];
  const float* beta    = (const float*)d_in[8];
  const float* mean    = (const float*)d_in[9];
  const float* var     = (const float*)d_in[10];
  float* out = (float*)d_out;

  cudaFuncSetAttribute(k_feats, cudaFuncAttributeMaxDynamicSharedMemorySize, (int)sizeof(SmemF));
  cudaFuncSetAttribute(k_attn,  cudaFuncAttributeMaxDynamicSharedMemorySize, (int)sizeof(SmemA));

  k_feats<<<dim3(NNODE/64, BB), 256, sizeof(SmemF)>>>(x, W, a_self, a_neigh);
  k_prep<<<BB*HH, 256>>>();
  k_attn<<<dim3(NNODE/IT, BB), 256, sizeof(SmemA)>>>(adj, msk, bias, gamma, beta, mean, var, out);
}